// round 1
// baseline (speedup 1.0000x reference)
#include <cuda_runtime.h>

// MKMMD loss, B=256, D=256, n=512, KERNEL_MUL=2, KERNEL_NUM=5, FIX_SIGMA=None.
//
// Math notes:
//  - sum(l2_cum) over the full (n,n,D) tensor = sum_e (D-e) * sum_{i,j}(v_i-v_j)^2
//    with sum_{i,j}(v_i-v_j)^2 = 2n*S2_e - 2*S1_e^2  (per feature column e).
//  - Only 4*B=1024 (row,row) pairs contribute to the loss.
//  - exp(-x/(bw*2^k)) = exp(-x/bw)^(2^-k): one exp + k repeated sqrts.

#define BB 256
#define DD 256
#define NROWS (2*BB)
#define WARPS_PER_BLOCK 8
#define NPAIRS (4*BB)
#define NBLOCKS (NPAIRS / WARPS_PER_BLOCK)   // 128

__device__ double       g_acc;
__device__ float        g_inv_bw;     // 1 / (bandwidth / 4)
__device__ unsigned int g_count;

// ---------------------------------------------------------------------------
// Kernel 1: bandwidth from analytic column statistics. One block, 256 threads,
// thread f owns feature column f (coalesced loads across threads).
// ---------------------------------------------------------------------------
__global__ void __launch_bounds__(DD) bw_kernel(const float* __restrict__ src,
                                                const float* __restrict__ tgt) {
    const int f = threadIdx.x;
    float s1 = 0.f, s2 = 0.f;
#pragma unroll 8
    for (int i = 0; i < BB; ++i) {
        float v = src[i * DD + f];
        s1 += v;
        s2 = fmaf(v, v, s2);
    }
#pragma unroll 8
    for (int i = 0; i < BB; ++i) {
        float v = tgt[i * DD + f];
        s1 += v;
        s2 = fmaf(v, v, s2);
    }
    // per-feature pairwise sq-dist sum, weighted by cumsum multiplicity (D - f)
    double colsum = 2.0 * (double)NROWS * (double)s2 - 2.0 * (double)s1 * (double)s1;
    double contrib = (double)(DD - f) * colsum;

    __shared__ double sh[DD];
    sh[f] = contrib;
    __syncthreads();
#pragma unroll
    for (int s = DD / 2; s > 0; s >>= 1) {
        if (f < s) sh[f] += sh[f + s];
        __syncthreads();
    }
    if (f == 0) {
        const double n  = (double)NROWS;
        double bw = sh[0] / (n * n - n);
        bw *= 0.25;                      // / KERNEL_MUL^(KERNEL_NUM//2) = /4
        g_inv_bw = (float)(1.0 / bw);
        g_acc    = 0.0;
        g_count  = 0u;
    }
}

// ---------------------------------------------------------------------------
// Kernel 2: warp per pair. 128 blocks x 256 threads (8 warps).
// ---------------------------------------------------------------------------
__global__ void __launch_bounds__(32 * WARPS_PER_BLOCK) loss_kernel(
    const float* __restrict__ src, const float* __restrict__ tgt,
    float* __restrict__ out) {
    const int warp = threadIdx.x >> 5;
    const int lane = threadIdx.x & 31;
    const int p    = blockIdx.x * WARPS_PER_BLOCK + warp;   // 0..1023
    const int grp  = p >> 8;                                // 0..3
    const int i    = p & (BB - 1);
    const int j    = (i + 1) & (BB - 1);

    const float* pa;
    const float* pb;
    float sign;
    if (grp == 0)      { pa = src + i * DD; pb = src + j * DD; sign =  1.f; }
    else if (grp == 1) { pa = tgt + i * DD; pb = tgt + j * DD; sign =  1.f; }
    else if (grp == 2) { pa = src + i * DD; pb = tgt + j * DD; sign = -1.f; }
    else               { pa = src + j * DD; pb = tgt + i * DD; sign = -1.f; }

    // Each lane handles 8 consecutive features: [8*lane, 8*lane+8).
    const float4* a4 = reinterpret_cast<const float4*>(pa) + lane * 2;
    const float4* b4 = reinterpret_cast<const float4*>(pb) + lane * 2;
    float4 a0 = a4[0], a1 = a4[1];
    float4 b0 = b4[0], b1 = b4[1];

    float sq[8];
    {
        float d0 = a0.x - b0.x, d1 = a0.y - b0.y, d2 = a0.z - b0.z, d3 = a0.w - b0.w;
        float d4 = a1.x - b1.x, d5 = a1.y - b1.y, d6 = a1.z - b1.z, d7 = a1.w - b1.w;
        sq[0] = d0 * d0; sq[1] = d1 * d1; sq[2] = d2 * d2; sq[3] = d3 * d3;
        sq[4] = d4 * d4; sq[5] = d5 * d5; sq[6] = d6 * d6; sq[7] = d7 * d7;
    }

    // in-lane inclusive prefix
    float run = 0.f;
#pragma unroll
    for (int k = 0; k < 8; ++k) { run += sq[k]; sq[k] = run; }

    // warp-level exclusive offset of lane totals
    float pref = run;
#pragma unroll
    for (int off = 1; off < 32; off <<= 1) {
        float y = __shfl_up_sync(0xffffffffu, pref, off);
        if (lane >= off) pref += y;
    }
    const float excl = pref - run;

    const float inv_bw = g_inv_bw;
    float lacc = 0.f;
#pragma unroll
    for (int k = 0; k < 8; ++k) {
        float x  = (sq[k] + excl) * inv_bw;   // exponent arg for k=0 kernel
        float e0 = __expf(-x);
        float e1 = sqrtf(e0);                 // exp(-x/2)
        float e2 = sqrtf(e1);                 // exp(-x/4)
        float e3 = sqrtf(e2);                 // exp(-x/8)
        float e4 = sqrtf(e3);                 // exp(-x/16)
        lacc += (e0 + e1) + (e2 + e3) + e4;
    }
    lacc *= sign;

    // warp reduce
#pragma unroll
    for (int off = 16; off > 0; off >>= 1)
        lacc += __shfl_xor_sync(0xffffffffu, lacc, off);

    __shared__ float wsum[WARPS_PER_BLOCK];
    if (lane == 0) wsum[warp] = lacc;
    __syncthreads();

    if (threadIdx.x == 0) {
        float bsum = 0.f;
#pragma unroll
        for (int w = 0; w < WARPS_PER_BLOCK; ++w) bsum += wsum[w];
        atomicAdd(&g_acc, (double)bsum);
        __threadfence();
        unsigned int t = atomicAdd(&g_count, 1u);
        if (t == (unsigned int)(gridDim.x - 1)) {
            __threadfence();
            double total = *((volatile double*)&g_acc);
            out[0] = (float)(total / (double)(BB * DD));
        }
    }
}

extern "C" void kernel_launch(void* const* d_in, const int* in_sizes, int n_in,
                              void* d_out, int out_size) {
    const float* src = (const float*)d_in[0];
    const float* tgt = (const float*)d_in[1];
    float* out = (float*)d_out;
    (void)in_sizes; (void)n_in; (void)out_size;

    bw_kernel<<<1, DD>>>(src, tgt);
    loss_kernel<<<NBLOCKS, 32 * WARPS_PER_BLOCK>>>(src, tgt, out);
}

// round 3
// speedup vs baseline: 2.0139x; 2.0139x over previous
#include <cuda_runtime.h>

// MKMMD loss, B=256, D=256, n=512, KERNEL_MUL=2, KERNEL_NUM=5, FIX_SIGMA=None.
//
// Math:
//  - sum(l2_cum) over (n,n,D) = sum_f (D-f) * (2n*S2_f - 2*S1_f^2)  (per-column stats)
//  - only 4B=1024 (row,row) pairs contribute to the loss
//  - exp(-x/(bw_base*2^k)) = e4^(2^(4-k)) with e4 = exp(-x/(16*bw_base)):
//    one __expf + 4 FMULs replaces 1 exp + 4 sqrt.

#define BB 256
#define DD 256
#define NROWS (2*BB)
#define WARPS_PER_BLOCK 8
#define NPAIRS (4*BB)
#define NBLOCKS (NPAIRS / WARPS_PER_BLOCK)   // 128

__device__ float        g_s1[DD];     // per-column sum over all 512 rows
__device__ double       g_ws2;        // sum_f (D-f)*S2_f (accumulated)
__device__ double       g_acc;        // loss accumulator
__device__ unsigned int g_count;

// ---------------------------------------------------------------------------
// Kernel 1: per-column statistics, full-chip parallel.
// 128 blocks x 256 threads; block b owns rows 4b..4b+3 (coalesced).
// ---------------------------------------------------------------------------
__global__ void __launch_bounds__(DD) stats_kernel(const float* __restrict__ src,
                                                   const float* __restrict__ tgt) {
    const int t = threadIdx.x;
    const int r0 = blockIdx.x * 4;

    float s1 = 0.f, s2 = 0.f;
#pragma unroll
    for (int k = 0; k < 4; ++k) {
        int r = r0 + k;
        const float* row = (r < BB) ? (src + r * DD) : (tgt + (r - BB) * DD);
        float v = row[t];
        s1 += v;
        s2 = fmaf(v, v, s2);
    }
    atomicAdd(&g_s1[t], s1);

    // weighted S2 partial: (D - t) * s2, reduced to one double atomic per block
    float term = (float)(DD - t) * s2;
#pragma unroll
    for (int off = 16; off > 0; off >>= 1)
        term += __shfl_xor_sync(0xffffffffu, term, off);

    __shared__ float wsum[WARPS_PER_BLOCK];
    const int warp = t >> 5, lane = t & 31;
    if (lane == 0) wsum[warp] = term;
    __syncthreads();
    if (t == 0) {
        float bsum = 0.f;
#pragma unroll
        for (int w = 0; w < WARPS_PER_BLOCK; ++w) bsum += wsum[w];
        atomicAdd(&g_ws2, (double)bsum);
    }
}

// ---------------------------------------------------------------------------
// Kernel 2: bandwidth finalize (redundant per block, from L2) + loss.
// 128 blocks x 256 threads; warp per pair.
// ---------------------------------------------------------------------------
__global__ void __launch_bounds__(32 * WARPS_PER_BLOCK) loss_kernel(
    const float* __restrict__ src, const float* __restrict__ tgt,
    float* __restrict__ out) {
    const int tid  = threadIdx.x;
    const int warp = tid >> 5;
    const int lane = tid & 31;

    __shared__ float sh_red[WARPS_PER_BLOCK];
    __shared__ float sh_inv16;   // 1/(16*bw_base) = 1/(4*bw)

    // ---- per-block bandwidth finalize (1 KB read from L2) ----
    {
        float s  = g_s1[tid];
        float tm = (float)(DD - tid) * s * s;     // (D-f) * S1_f^2
#pragma unroll
        for (int off = 16; off > 0; off >>= 1)
            tm += __shfl_xor_sync(0xffffffffu, tm, off);
        if (lane == 0) sh_red[warp] = tm;
        __syncthreads();
        if (tid == 0) {
            float s1sq = 0.f;
#pragma unroll
            for (int w = 0; w < WARPS_PER_BLOCK; ++w) s1sq += sh_red[w];
            const double n = (double)NROWS;
            double bwsum = 2.0 * n * g_ws2 - 2.0 * (double)s1sq;
            double bw    = bwsum / (n * n - n);   // reference bandwidth
            // bw_base = bw/4; arg scale = 1/(16*bw_base) = 1/(4*bw)
            sh_inv16 = (float)(1.0 / (4.0 * bw));
        }
        __syncthreads();
    }
    const float inv16 = sh_inv16;

    // ---- loss: warp per pair ----
    const int p   = blockIdx.x * WARPS_PER_BLOCK + warp;   // 0..1023
    const int grp = p >> 8;                                // 0..3
    const int i   = p & (BB - 1);
    const int j   = (i + 1) & (BB - 1);

    const float* pa;
    const float* pb;
    float sign;
    if (grp == 0)      { pa = src + i * DD; pb = src + j * DD; sign =  1.f; }
    else if (grp == 1) { pa = tgt + i * DD; pb = tgt + j * DD; sign =  1.f; }
    else if (grp == 2) { pa = src + i * DD; pb = tgt + j * DD; sign = -1.f; }
    else               { pa = src + j * DD; pb = tgt + i * DD; sign = -1.f; }

    const float4* a4 = reinterpret_cast<const float4*>(pa) + lane * 2;
    const float4* b4 = reinterpret_cast<const float4*>(pb) + lane * 2;
    float4 a0 = a4[0], a1 = a4[1];
    float4 b0 = b4[0], b1 = b4[1];

    float sq[8];
    {
        float d0 = a0.x - b0.x, d1 = a0.y - b0.y, d2 = a0.z - b0.z, d3 = a0.w - b0.w;
        float d4 = a1.x - b1.x, d5 = a1.y - b1.y, d6 = a1.z - b1.z, d7 = a1.w - b1.w;
        sq[0] = d0 * d0; sq[1] = d1 * d1; sq[2] = d2 * d2; sq[3] = d3 * d3;
        sq[4] = d4 * d4; sq[5] = d5 * d5; sq[6] = d6 * d6; sq[7] = d7 * d7;
    }

    // in-lane inclusive prefix over 8 features
    float run = 0.f;
#pragma unroll
    for (int k = 0; k < 8; ++k) { run += sq[k]; sq[k] = run; }

    // warp exclusive scan of lane totals
    float pref = run;
#pragma unroll
    for (int off = 1; off < 32; off <<= 1) {
        float y = __shfl_up_sync(0xffffffffu, pref, off);
        if (lane >= off) pref += y;
    }
    const float excl = pref - run;

    float lacc = 0.f;
#pragma unroll
    for (int k = 0; k < 8; ++k) {
        float y  = (sq[k] + excl) * inv16;   // x/(16*bw_base)
        float e4 = __expf(-y);               // exp(-x/(16 bb))
        float s  = e4;
        float t2 = e4 * e4;  s += t2;        // exp(-x/(8 bb))
        t2 *= t2;            s += t2;        // exp(-x/(4 bb))
        t2 *= t2;            s += t2;        // exp(-x/(2 bb))
        t2 *= t2;            s += t2;        // exp(-x/bb)
        lacc += s;
    }
    lacc *= sign;

#pragma unroll
    for (int off = 16; off > 0; off >>= 1)
        lacc += __shfl_xor_sync(0xffffffffu, lacc, off);

    if (lane == 0) sh_red[warp] = lacc;
    __syncthreads();

    __shared__ bool sh_final;
    if (tid == 0) {
        float bsum = 0.f;
#pragma unroll
        for (int w = 0; w < WARPS_PER_BLOCK; ++w) bsum += sh_red[w];
        atomicAdd(&g_acc, (double)bsum);
        __threadfence();
        unsigned int c = atomicAdd(&g_count, 1u);
        sh_final = (c == (unsigned int)(gridDim.x - 1));
    }
    __syncthreads();

    // Final block: write output and reset globals for the next graph replay.
    if (sh_final) {
        if (tid == 0) {
            __threadfence();
            double total = *((volatile double*)&g_acc);
            out[0] = (float)(total / (double)(BB * DD));
            g_acc   = 0.0;
            g_ws2   = 0.0;
            g_count = 0u;
        }
        g_s1[tid] = 0.f;
    }
}

extern "C" void kernel_launch(void* const* d_in, const int* in_sizes, int n_in,
                              void* d_out, int out_size) {
    const float* src = (const float*)d_in[0];
    const float* tgt = (const float*)d_in[1];
    float* out = (float*)d_out;
    (void)in_sizes; (void)n_in; (void)out_size;

    stats_kernel<<<NBLOCKS, DD>>>(src, tgt);
    loss_kernel<<<NBLOCKS, 32 * WARPS_PER_BLOCK>>>(src, tgt, out);
}